// round 5
// baseline (speedup 1.0000x reference)
#include <cuda_runtime.h>
#include <cstdint>

#define NB 4
#define NN 2048
#define NC 256
#define NH 4
#define HD 64

// ---- scratch (allocation-free) ----
__device__ float g_X[NB*NN*NC];
__device__ float g_q[NB*NN*NC];
__device__ float g_k[NB*NN*NC];
__device__ float g_Y[NB*NN*NC];
__device__ float g_dis[NB*NH*NN];

__device__ __forceinline__ float to_tf32(float x) {
    uint32_t u;
    asm("cvt.rna.tf32.f32 %0, %1;" : "=r"(u) : "f"(x));
    return __uint_as_float(u);
}
__device__ __forceinline__ void mma_tf32(float c[4], const uint32_t a[4], const uint32_t b[2]) {
    asm volatile(
        "mma.sync.aligned.m16n8k8.row.col.f32.tf32.tf32.f32 "
        "{%0,%1,%2,%3}, {%4,%5,%6,%7}, {%8,%9}, {%0,%1,%2,%3};"
        : "+f"(c[0]), "+f"(c[1]), "+f"(c[2]), "+f"(c[3])
        : "r"(a[0]), "r"(a[1]), "r"(a[2]), "r"(a[3]), "r"(b[0]), "r"(b[1]));
}
__device__ __forceinline__ float sigw(float a, float s) {
    float e = __expf(-0.125f * s);
    return __fdividef(a, 1.f + e);
}

// ============================================================
// K1 (mma tf32): out = lrelu(A[8192,256] @ W[256,256] (+bias)), z selects W
// CTA 128x128, K-chunks 32, 8 warps (warp tile 32x64)
// ============================================================
__global__ __launch_bounds__(256) void k1_mma(const float* __restrict__ A,
                                              const float* __restrict__ W0,
                                              const float* __restrict__ W1,
                                              const float* __restrict__ W2,
                                              const float* __restrict__ bias) {
    const int z = blockIdx.z;
    const float* Wm = (z == 0) ? W0 : ((z == 1) ? W1 : W2);
    float* outp = (z == 0) ? g_X : ((z == 1) ? g_q : g_k);
    __shared__ float As[128*36];
    __shared__ float Bs[128*33];
    const int tid = threadIdx.x;
    const int wid = tid >> 5, lid = tid & 31;
    const int grp = lid >> 2, tg = lid & 3;
    const int wm = wid >> 1, wn = wid & 1;
    const int M0 = blockIdx.y * 128, N0 = blockIdx.x * 128;
    float acc[2][8][4] = {};
    for (int kc = 0; kc < 8; kc++) {
        const int k0 = kc * 32;
        __syncthreads();
        #pragma unroll
        for (int p = 0; p < 4; p++) {   // A: 128 rows x 32 k
            int idx = tid + 256*p;
            int f = idx & 7, row = idx >> 3;
            float4 v = *(const float4*)(A + (size_t)(M0 + row)*NC + k0 + f*4);
            float* d = As + row*36 + f*4;
            d[0]=to_tf32(v.x); d[1]=to_tf32(v.y); d[2]=to_tf32(v.z); d[3]=to_tf32(v.w);
        }
        #pragma unroll
        for (int p = 0; p < 4; p++) {   // B: W[k][n] -> Bs[n][k] transposed
            int idx = tid + 256*p;
            int f = idx & 31, krow = idx >> 5;
            float4 v = *(const float4*)(Wm + (size_t)(k0 + krow)*NC + N0 + f*4);
            Bs[(f*4+0)*33 + krow] = to_tf32(v.x);
            Bs[(f*4+1)*33 + krow] = to_tf32(v.y);
            Bs[(f*4+2)*33 + krow] = to_tf32(v.z);
            Bs[(f*4+3)*33 + krow] = to_tf32(v.w);
        }
        __syncthreads();
        #pragma unroll
        for (int kk = 0; kk < 4; kk++) {
            uint32_t a[2][4], bf[8][2];
            #pragma unroll
            for (int i = 0; i < 2; i++) {
                const float* ap = As + (wm*32 + i*16 + grp)*36 + kk*8 + tg;
                a[i][0] = __float_as_uint(ap[0]);
                a[i][1] = __float_as_uint(ap[8*36]);
                a[i][2] = __float_as_uint(ap[4]);
                a[i][3] = __float_as_uint(ap[8*36 + 4]);
            }
            #pragma unroll
            for (int j = 0; j < 8; j++) {
                const float* bp = Bs + (wn*64 + j*8 + grp)*33 + kk*8 + tg;
                bf[j][0] = __float_as_uint(bp[0]);
                bf[j][1] = __float_as_uint(bp[4]);
            }
            #pragma unroll
            for (int i = 0; i < 2; i++)
                #pragma unroll
                for (int j = 0; j < 8; j++)
                    mma_tf32(acc[i][j], a[i], bf[j]);
        }
    }
    #pragma unroll
    for (int i = 0; i < 2; i++)
        #pragma unroll
        for (int u = 0; u < 2; u++) {
            int row = M0 + wm*32 + i*16 + grp + u*8;
            #pragma unroll
            for (int j = 0; j < 8; j++) {
                int col = N0 + wn*64 + j*8 + tg*2;
                float v0 = acc[i][j][u*2], v1 = acc[i][j][u*2+1];
                if (z == 0) { v0 += bias[col]; v1 += bias[col+1]; }
                v0 = (v0 >= 0.f) ? v0 : 0.01f*v0;
                v1 = (v1 >= 0.f) ? v1 : 0.01f*v1;
                *(float2*)(outp + (size_t)row*NC + col) = make_float2(v0, v1);
            }
        }
}

// ============================================================
// K2 (deg only): dis[b,h,x] = rsqrt(sum_y adj*sigmoid(q.k/8))
// ============================================================
__global__ __launch_bounds__(256) void k2_deg(const float* __restrict__ adj) {
    extern __shared__ float sm[];
    float* qs  = sm;                  // 128*68
    float* ks  = sm + 128*68;         // 128*68
    float* red = sm + 2*128*68;       // 4*128
    const int tid = threadIdx.x;
    const int wid = tid >> 5, lid = tid & 31;
    const int grp = lid >> 2, tg = lid & 3;
    const int wm = wid >> 2, wn = wid & 3;
    const int bh = blockIdx.y;
    const int b = bh >> 2, h = bh & 3;
    const int x0 = blockIdx.x * 128;

    {
        int f = tid & 15, r0 = tid >> 4;
        const float* src = g_q + ((size_t)(b*NN) + x0)*NC + h*HD;
        #pragma unroll
        for (int p = 0; p < 8; p++) {
            int row = p*16 + r0;
            float4 v = *(const float4*)(src + (size_t)row*NC + f*4);
            float* d = qs + row*68 + f*4;
            d[0]=to_tf32(v.x); d[1]=to_tf32(v.y); d[2]=to_tf32(v.z); d[3]=to_tf32(v.w);
        }
    }
    const float* ksrc  = g_k + (size_t)b*NN*NC + h*HD;
    const float* abase = adj + (size_t)b*NN*NN;
    float dsum[4][2] = {};

    for (int yt = 0; yt < NN/128; yt++) {
        const int y0 = yt * 128;
        __syncthreads();
        {
            int f = tid & 15, r0 = tid >> 4;
            #pragma unroll
            for (int p = 0; p < 8; p++) {
                int row = p*16 + r0;
                float4 v = *(const float4*)(ksrc + (size_t)(y0+row)*NC + f*4);
                float* d = ks + row*68 + f*4;
                d[0]=to_tf32(v.x); d[1]=to_tf32(v.y); d[2]=to_tf32(v.z); d[3]=to_tf32(v.w);
            }
        }
        __syncthreads();
        float acc[4][4][4] = {};
        #pragma unroll
        for (int kk = 0; kk < 8; kk++) {
            uint32_t a[4][4], bf[4][2];
            #pragma unroll
            for (int i = 0; i < 4; i++) {
                const float* ap = qs + (wm*64 + i*16)*68 + kk*8;
                a[i][0] = __float_as_uint(ap[grp*68 + tg]);
                a[i][1] = __float_as_uint(ap[(grp+8)*68 + tg]);
                a[i][2] = __float_as_uint(ap[grp*68 + tg + 4]);
                a[i][3] = __float_as_uint(ap[(grp+8)*68 + tg + 4]);
            }
            #pragma unroll
            for (int j = 0; j < 4; j++) {
                const float* bp = ks + (wn*32 + j*8 + grp)*68 + kk*8;
                bf[j][0] = __float_as_uint(bp[tg]);
                bf[j][1] = __float_as_uint(bp[tg + 4]);
            }
            #pragma unroll
            for (int i = 0; i < 4; i++)
                #pragma unroll
                for (int j = 0; j < 4; j++)
                    mma_tf32(acc[i][j], a[i], bf[j]);
        }
        #pragma unroll
        for (int i = 0; i < 4; i++)
            #pragma unroll
            for (int u = 0; u < 2; u++) {
                int xr = x0 + wm*64 + i*16 + grp + u*8;
                const float* ar = abase + (size_t)xr*NN + y0 + wn*32 + tg*2;
                float lsum = 0.f;
                #pragma unroll
                for (int j = 0; j < 4; j++) {
                    float2 av = *(const float2*)(ar + j*8);
                    lsum += sigw(av.x, acc[i][j][u*2+0])
                          + sigw(av.y, acc[i][j][u*2+1]);
                }
                dsum[i][u] += lsum;
            }
    }
    #pragma unroll
    for (int i = 0; i < 4; i++)
        #pragma unroll
        for (int u = 0; u < 2; u++) {
            float v = dsum[i][u];
            v += __shfl_xor_sync(0xffffffffu, v, 1);
            v += __shfl_xor_sync(0xffffffffu, v, 2);
            if (tg == 0) red[wn*128 + wm*64 + i*16 + grp + u*8] = v;
        }
    __syncthreads();
    if (tid < 128) {
        float v = red[tid] + red[128+tid] + red[256+tid] + red[384+tid];
        g_dis[bh*NN + x0 + tid] = (v > 0.f) ? rsqrtf(v) : 0.f;
    }
}

// ============================================================
// K3 (fused): Y[x,d] = dis_x * sum_y (adj*sigmoid(q.k/8))[x,y] * dis_y * X[y,d]
// CTA 256 thr, x-tile 128, y-tiles of 64; W recomputed through per-warp smem
// ============================================================
__global__ __launch_bounds__(256) void k3_fused(const float* __restrict__ adj) {
    extern __shared__ float sm[];
    float* qs = sm;                   // 128*68
    float* ks = sm + 128*68;          // 64*68
    float* Ws = sm + 128*68 + 64*68;  // 128*68 (per-warp private rows)
    float* Xs = sm + 2*128*68 + 64*68;// 64*68  (dis_y folded)
    const int tid = threadIdx.x;
    const int wid = tid >> 5, lid = tid & 31;
    const int grp = lid >> 2, tg = lid & 3;
    const int bh = blockIdx.y;
    const int b = bh >> 2, h = bh & 3;
    const int x0 = blockIdx.x * 128;

    {   // stage q once
        int f = tid & 15, r0 = tid >> 4;
        const float* src = g_q + ((size_t)(b*NN) + x0)*NC + h*HD;
        #pragma unroll
        for (int p = 0; p < 8; p++) {
            int row = p*16 + r0;
            float4 v = *(const float4*)(src + (size_t)row*NC + f*4);
            float* d = qs + row*68 + f*4;
            d[0]=to_tf32(v.x); d[1]=to_tf32(v.y); d[2]=to_tf32(v.z); d[3]=to_tf32(v.w);
        }
    }
    const float* ksrc  = g_k + (size_t)b*NN*NC + h*HD;
    const float* xsrc  = g_X + (size_t)b*NN*NC + h*HD;
    const float* abase = adj + (size_t)b*NN*NN;
    const float* disb  = g_dis + bh*NN;
    float yacc[8][4] = {};

    for (int yt = 0; yt < NN/64; yt++) {
        const int y0 = yt * 64;
        __syncthreads();
        {   // stage k tile 64x64
            int f = tid & 15, r0 = tid >> 4;
            #pragma unroll
            for (int p = 0; p < 4; p++) {
                int row = p*16 + r0;
                float4 v = *(const float4*)(ksrc + (size_t)(y0+row)*NC + f*4);
                float* d = ks + row*68 + f*4;
                d[0]=to_tf32(v.x); d[1]=to_tf32(v.y); d[2]=to_tf32(v.z); d[3]=to_tf32(v.w);
            }
        }
        {   // stage Xs[d][y] = tf32(dis_y * X[y,d]) (transposed)
            int y = tid & 63, dblk = (tid >> 6) * 16;
            float dy = disb[y0 + y];
            const float* xr = xsrc + (size_t)(y0+y)*NC + dblk;
            #pragma unroll
            for (int u = 0; u < 4; u++) {
                float4 v = *(const float4*)(xr + u*4);
                Xs[(dblk+u*4+0)*68 + y] = to_tf32(v.x*dy);
                Xs[(dblk+u*4+1)*68 + y] = to_tf32(v.y*dy);
                Xs[(dblk+u*4+2)*68 + y] = to_tf32(v.z*dy);
                Xs[(dblk+u*4+3)*68 + y] = to_tf32(v.w*dy);
            }
        }
        __syncthreads();
        // ---- S = q.k^T for this warp's 16 rows x 64 cols ----
        float sacc[8][4] = {};
        #pragma unroll
        for (int kk = 0; kk < 8; kk++) {
            uint32_t a[4], bf[8][2];
            const float* ap = qs + (wid*16 + grp)*68 + kk*8 + tg;
            a[0] = __float_as_uint(ap[0]);
            a[1] = __float_as_uint(ap[8*68]);
            a[2] = __float_as_uint(ap[4]);
            a[3] = __float_as_uint(ap[8*68 + 4]);
            #pragma unroll
            for (int j = 0; j < 8; j++) {
                const float* bp = ks + (j*8 + grp)*68 + kk*8;
                bf[j][0] = __float_as_uint(bp[tg]);
                bf[j][1] = __float_as_uint(bp[tg + 4]);
            }
            #pragma unroll
            for (int j = 0; j < 8; j++) mma_tf32(sacc[j], a, bf[j]);
        }
        // ---- epilogue: w = adj*sigmoid -> Ws (warp-private rows, no sync) ----
        #pragma unroll
        for (int u = 0; u < 2; u++) {
            int row = wid*16 + grp + u*8;
            const float* ar = abase + (size_t)(x0+row)*NN + y0 + tg*2;
            float* wr = Ws + row*68 + tg*2;
            #pragma unroll
            for (int j = 0; j < 8; j++) {
                float2 av = *(const float2*)(ar + j*8);
                float w0 = sigw(av.x, sacc[j][u*2+0]);
                float w1 = sigw(av.y, sacc[j][u*2+1]);
                *(float2*)(wr + j*8) = make_float2(to_tf32(w0), to_tf32(w1));
            }
        }
        // ---- Y += Ws(own rows) @ Xs ----
        #pragma unroll
        for (int kk = 0; kk < 8; kk++) {
            uint32_t a[4], bf[8][2];
            const float* ap = Ws + (wid*16 + grp)*68 + kk*8 + tg;
            a[0] = __float_as_uint(ap[0]);
            a[1] = __float_as_uint(ap[8*68]);
            a[2] = __float_as_uint(ap[4]);
            a[3] = __float_as_uint(ap[8*68 + 4]);
            #pragma unroll
            for (int j = 0; j < 8; j++) {
                const float* bp = Xs + (j*8 + grp)*68 + kk*8;
                bf[j][0] = __float_as_uint(bp[tg]);
                bf[j][1] = __float_as_uint(bp[tg + 4]);
            }
            #pragma unroll
            for (int j = 0; j < 8; j++) mma_tf32(yacc[j], a, bf[j]);
        }
    }
    // ---- store Y * dis_x ----
    #pragma unroll
    for (int u = 0; u < 2; u++) {
        int x = x0 + wid*16 + grp + u*8;
        float dx = disb[x];
        float* dst = g_Y + (size_t)(b*NN + x)*NC + h*HD + tg*2;
        #pragma unroll
        for (int j = 0; j < 8; j++)
            *(float2*)(dst + j*8) = make_float2(yacc[j][u*2]*dx, yacc[j][u*2+1]*dx);
    }
}

// ============================================================
// K5: LayerNorm over last dim (256), warp per row
// ============================================================
__global__ __launch_bounds__(256) void k5_ln(const float* __restrict__ g,
                                             const float* __restrict__ bta,
                                             float* __restrict__ out) {
    int gw = (blockIdx.x * 256 + threadIdx.x) >> 5;
    int lane = threadIdx.x & 31;
    if (gw >= NB*NN) return;
    const float* row = g_Y + (size_t)gw * NC;
    float4 v0 = *(const float4*)(row + lane*8);
    float4 v1 = *(const float4*)(row + lane*8 + 4);
    float s  = (v0.x+v0.y) + (v0.z+v0.w) + (v1.x+v1.y) + (v1.z+v1.w);
    float s2 = v0.x*v0.x + v0.y*v0.y + v0.z*v0.z + v0.w*v0.w
             + v1.x*v1.x + v1.y*v1.y + v1.z*v1.z + v1.w*v1.w;
    #pragma unroll
    for (int o = 16; o; o >>= 1) {
        s  += __shfl_xor_sync(0xffffffffu, s,  o);
        s2 += __shfl_xor_sync(0xffffffffu, s2, o);
    }
    float mu  = s * (1.f/NC);
    float var = s2 * (1.f/NC) - mu * mu;
    float inv = rsqrtf(var + 1e-5f);
    int c = lane * 8;
    float4 g0 = *(const float4*)(g + c),   g1 = *(const float4*)(g + c + 4);
    float4 b0 = *(const float4*)(bta + c), b1 = *(const float4*)(bta + c + 4);
    float4 o0, o1;
    o0.x = (v0.x-mu)*inv*g0.x + b0.x;  o0.y = (v0.y-mu)*inv*g0.y + b0.y;
    o0.z = (v0.z-mu)*inv*g0.z + b0.z;  o0.w = (v0.w-mu)*inv*g0.w + b0.w;
    o1.x = (v1.x-mu)*inv*g1.x + b1.x;  o1.y = (v1.y-mu)*inv*g1.y + b1.y;
    o1.z = (v1.z-mu)*inv*g1.z + b1.z;  o1.w = (v1.w-mu)*inv*g1.w + b1.w;
    *(float4*)(out + (size_t)gw*NC + c)     = o0;
    *(float4*)(out + (size_t)gw*NC + c + 4) = o1;
}

extern "C" void kernel_launch(void* const* d_in, const int* in_sizes, int n_in,
                              void* d_out, int out_size) {
    const float* node = (const float*)d_in[0];
    const float* adj  = (const float*)d_in[1];
    const float* Wlin = (const float*)d_in[2];
    const float* blin = (const float*)d_in[3];
    const float* Wq   = (const float*)d_in[4];
    const float* Wk   = (const float*)d_in[5];
    const float* lng  = (const float*)d_in[6];
    const float* lnb  = (const float*)d_in[7];
    float* out = (float*)d_out;

    const int smem_k2 = (2*128*68 + 4*128) * 4;            // 71,680 B
    const int smem_k3 = (2*128*68 + 2*64*68) * 4;          // 104,448 B
    cudaFuncSetAttribute(k2_deg,   cudaFuncAttributeMaxDynamicSharedMemorySize, smem_k2);
    cudaFuncSetAttribute(k3_fused, cudaFuncAttributeMaxDynamicSharedMemorySize, smem_k3);

    dim3 g1(NC/128, (NB*NN)/128, 3);
    k1_mma<<<g1, 256>>>(node, Wlin, Wq, Wk, blin);

    dim3 g2(NN/128, NB*NH);
    k2_deg<<<g2, 256, smem_k2>>>(adj);

    dim3 g3(NN/128, NB*NH);
    k3_fused<<<g3, 256, smem_k3>>>(adj);

    k5_ln<<<(NB*NN)/8, 256>>>(lng, lnb, out);
}

// round 7
// speedup vs baseline: 1.1278x; 1.1278x over previous
#include <cuda_runtime.h>
#include <cuda_fp16.h>
#include <cstdint>

#define NB 4
#define NN 2048
#define NC 256
#define NH 4
#define HD 64

// ---- scratch (allocation-free) ----
__device__ float g_X[NB*NN*NC];
__device__ float g_q[NB*NN*NC];
__device__ float g_k[NB*NN*NC];
__device__ float g_Y[NB*NN*NC];
__device__ float g_dis[NB*NH*NN];
__device__ __half g_Wh[(size_t)NB*NH*NN*NN];   // 128MB fp16

__device__ __forceinline__ float to_tf32(float x) {
    uint32_t u;
    asm("cvt.rna.tf32.f32 %0, %1;" : "=r"(u) : "f"(x));
    return __uint_as_float(u);
}
__device__ __forceinline__ void mma_tf32(float c[4], const uint32_t a[4], const uint32_t b[2]) {
    asm volatile(
        "mma.sync.aligned.m16n8k8.row.col.f32.tf32.tf32.f32 "
        "{%0,%1,%2,%3}, {%4,%5,%6,%7}, {%8,%9}, {%0,%1,%2,%3};"
        : "+f"(c[0]), "+f"(c[1]), "+f"(c[2]), "+f"(c[3])
        : "r"(a[0]), "r"(a[1]), "r"(a[2]), "r"(a[3]), "r"(b[0]), "r"(b[1]));
}
// a * sigmoid(s/8), accurate (~1e-6 rel): proven 2.3e-4 pipeline error in R4
__device__ __forceinline__ float sigw(float a, float s) {
    float e = __expf(-0.125f * s);
    return __fdividef(a, 1.f + e);
}

// ============================================================
// K1 (mma tf32): out = lrelu(A[8192,256] @ W[256,256] (+bias)), z selects W
// ============================================================
__global__ __launch_bounds__(256) void k1_mma(const float* __restrict__ A,
                                              const float* __restrict__ W0,
                                              const float* __restrict__ W1,
                                              const float* __restrict__ W2,
                                              const float* __restrict__ bias) {
    const int z = blockIdx.z;
    const float* Wm = (z == 0) ? W0 : ((z == 1) ? W1 : W2);
    float* outp = (z == 0) ? g_X : ((z == 1) ? g_q : g_k);
    __shared__ float As[128*36];
    __shared__ float Bs[128*33];
    const int tid = threadIdx.x;
    const int wid = tid >> 5, lid = tid & 31;
    const int grp = lid >> 2, tg = lid & 3;
    const int wm = wid >> 1, wn = wid & 1;
    const int M0 = blockIdx.y * 128, N0 = blockIdx.x * 128;
    float acc[2][8][4] = {};
    for (int kc = 0; kc < 8; kc++) {
        const int k0 = kc * 32;
        __syncthreads();
        #pragma unroll
        for (int p = 0; p < 4; p++) {
            int idx = tid + 256*p;
            int f = idx & 7, row = idx >> 3;
            float4 v = *(const float4*)(A + (size_t)(M0 + row)*NC + k0 + f*4);
            float* d = As + row*36 + f*4;
            d[0]=to_tf32(v.x); d[1]=to_tf32(v.y); d[2]=to_tf32(v.z); d[3]=to_tf32(v.w);
        }
        #pragma unroll
        for (int p = 0; p < 4; p++) {
            int idx = tid + 256*p;
            int f = idx & 31, krow = idx >> 5;
            float4 v = *(const float4*)(Wm + (size_t)(k0 + krow)*NC + N0 + f*4);
            Bs[(f*4+0)*33 + krow] = to_tf32(v.x);
            Bs[(f*4+1)*33 + krow] = to_tf32(v.y);
            Bs[(f*4+2)*33 + krow] = to_tf32(v.z);
            Bs[(f*4+3)*33 + krow] = to_tf32(v.w);
        }
        __syncthreads();
        #pragma unroll
        for (int kk = 0; kk < 4; kk++) {
            uint32_t a[2][4], bf[8][2];
            #pragma unroll
            for (int i = 0; i < 2; i++) {
                const float* ap = As + (wm*32 + i*16 + grp)*36 + kk*8 + tg;
                a[i][0] = __float_as_uint(ap[0]);
                a[i][1] = __float_as_uint(ap[8*36]);
                a[i][2] = __float_as_uint(ap[4]);
                a[i][3] = __float_as_uint(ap[8*36 + 4]);
            }
            #pragma unroll
            for (int j = 0; j < 8; j++) {
                const float* bp = Bs + (wn*64 + j*8 + grp)*33 + kk*8 + tg;
                bf[j][0] = __float_as_uint(bp[0]);
                bf[j][1] = __float_as_uint(bp[4]);
            }
            #pragma unroll
            for (int i = 0; i < 2; i++)
                #pragma unroll
                for (int j = 0; j < 8; j++)
                    mma_tf32(acc[i][j], a[i], bf[j]);
        }
    }
    #pragma unroll
    for (int i = 0; i < 2; i++)
        #pragma unroll
        for (int u = 0; u < 2; u++) {
            int row = M0 + wm*32 + i*16 + grp + u*8;
            #pragma unroll
            for (int j = 0; j < 8; j++) {
                int col = N0 + wn*64 + j*8 + tg*2;
                float v0 = acc[i][j][u*2], v1 = acc[i][j][u*2+1];
                if (z == 0) { v0 += bias[col]; v1 += bias[col+1]; }
                v0 = (v0 >= 0.f) ? v0 : 0.01f*v0;
                v1 = (v1 >= 0.f) ? v1 : 0.01f*v1;
                *(float2*)(outp + (size_t)row*NC + col) = make_float2(v0, v1);
            }
        }
}

// ============================================================
// K2 (mma tf32): W[b,h,x,y] = adj*sigmoid(q.k/8) -> fp16; dis = rsqrt(rowsum)
// CTA 256 thr, tile 128x128, K=64
// ============================================================
__global__ __launch_bounds__(256) void k2_att_mma(const float* __restrict__ adj) {
    extern __shared__ float sm[];
    float* qs  = sm;                  // 128*68
    float* ks  = sm + 128*68;         // 128*68
    float* red = sm + 2*128*68;       // 4*128
    const int tid = threadIdx.x;
    const int wid = tid >> 5, lid = tid & 31;
    const int grp = lid >> 2, tg = lid & 3;
    const int wm = wid >> 2, wn = wid & 3;
    const int bh = blockIdx.y;
    const int b = bh >> 2, h = bh & 3;
    const int x0 = blockIdx.x * 128;

    {   // stage q (tf32-rounded)
        int f = tid & 15, r0 = tid >> 4;
        const float* src = g_q + ((size_t)(b*NN) + x0)*NC + h*HD;
        #pragma unroll
        for (int p = 0; p < 8; p++) {
            int row = p*16 + r0;
            float4 v = *(const float4*)(src + (size_t)row*NC + f*4);
            float* d = qs + row*68 + f*4;
            d[0]=to_tf32(v.x); d[1]=to_tf32(v.y); d[2]=to_tf32(v.z); d[3]=to_tf32(v.w);
        }
    }
    const float* ksrc  = g_k + (size_t)b*NN*NC + h*HD;
    const float* abase = adj + (size_t)b*NN*NN;
    __half* wbase = g_Wh + (size_t)bh*NN*NN;
    float dsum[4][2] = {};

    for (int yt = 0; yt < NN/128; yt++) {
        const int y0 = yt * 128;
        __syncthreads();
        {   // stage k tile
            int f = tid & 15, r0 = tid >> 4;
            #pragma unroll
            for (int p = 0; p < 8; p++) {
                int row = p*16 + r0;
                float4 v = *(const float4*)(ksrc + (size_t)(y0+row)*NC + f*4);
                float* d = ks + row*68 + f*4;
                d[0]=to_tf32(v.x); d[1]=to_tf32(v.y); d[2]=to_tf32(v.z); d[3]=to_tf32(v.w);
            }
        }
        __syncthreads();
        float acc[4][4][4] = {};
        #pragma unroll
        for (int kk = 0; kk < 8; kk++) {
            uint32_t a[4][4], bf[4][2];
            #pragma unroll
            for (int i = 0; i < 4; i++) {
                const float* ap = qs + (wm*64 + i*16)*68 + kk*8;
                a[i][0] = __float_as_uint(ap[grp*68 + tg]);
                a[i][1] = __float_as_uint(ap[(grp+8)*68 + tg]);
                a[i][2] = __float_as_uint(ap[grp*68 + tg + 4]);
                a[i][3] = __float_as_uint(ap[(grp+8)*68 + tg + 4]);
            }
            #pragma unroll
            for (int j = 0; j < 4; j++) {
                const float* bp = ks + (wn*32 + j*8 + grp)*68 + kk*8;
                bf[j][0] = __float_as_uint(bp[tg]);
                bf[j][1] = __float_as_uint(bp[tg + 4]);
            }
            #pragma unroll
            for (int i = 0; i < 4; i++)
                #pragma unroll
                for (int j = 0; j < 4; j++)
                    mma_tf32(acc[i][j], a[i], bf[j]);
        }
        // epilogue: sigmoid*adj -> fp16 W, accumulate degree in fp32
        #pragma unroll
        for (int i = 0; i < 4; i++) {
            #pragma unroll
            for (int u = 0; u < 2; u++) {
                int xr = x0 + wm*64 + i*16 + grp + u*8;
                const float* ar = abase + (size_t)xr*NN + y0 + wn*32 + tg*2;
                __half* wr = wbase + (size_t)xr*NN + y0 + wn*32 + tg*2;
                float lsum = 0.f;
                #pragma unroll
                for (int j = 0; j < 4; j++) {
                    float2 av = *(const float2*)(ar + j*8);
                    float w0 = sigw(av.x, acc[i][j][u*2+0]);
                    float w1 = sigw(av.y, acc[i][j][u*2+1]);
                    *(__half2*)(wr + j*8) = __float22half2_rn(make_float2(w0, w1));
                    lsum += w0 + w1;
                }
                dsum[i][u] += lsum;
            }
        }
    }
    #pragma unroll
    for (int i = 0; i < 4; i++)
        #pragma unroll
        for (int u = 0; u < 2; u++) {
            float v = dsum[i][u];
            v += __shfl_xor_sync(0xffffffffu, v, 1);
            v += __shfl_xor_sync(0xffffffffu, v, 2);
            if (tg == 0) red[wn*128 + wm*64 + i*16 + grp + u*8] = v;
        }
    __syncthreads();
    if (tid < 128) {
        float v = red[tid] + red[128+tid] + red[256+tid] + red[384+tid];
        g_dis[bh*NN + x0 + tid] = (v > 0.f) ? rsqrtf(v) : 0.f;
    }
}

// ============================================================
// K4 (mma tf32): Y[x,d] = dis_x * sum_y W[x,y]*dis_y*X[y,d], W from fp16
// CTA 256 thr, tile 128x64, K-chunks of 64 over y
// ============================================================
__global__ __launch_bounds__(256) void k4_agg_mma() {
    extern __shared__ float sm[];
    float* Ws = sm;                  // 128*68
    float* Xs = sm + 128*68;         // 64*68
    const int tid = threadIdx.x;
    const int wid = tid >> 5, lid = tid & 31;
    const int grp = lid >> 2, tg = lid & 3;
    const int wm = wid >> 1, wn = wid & 1;
    const int bh = blockIdx.y;
    const int b = bh >> 2, h = bh & 3;
    const int x0 = blockIdx.x * 128;
    const __half* wsrc = g_Wh + (size_t)bh*NN*NN + (size_t)x0*NN;
    const float* xsrc = g_X + (size_t)b*NN*NC + h*HD;
    const float* disb = g_dis + bh*NN;
    float acc[2][4][4] = {};
    for (int y0 = 0; y0 < NN; y0 += 64) {
        __syncthreads();
        {   // Ws: 128 rows x 64 fp16 cols -> f32 (exact; fp16 subset of tf32)
            #pragma unroll
            for (int p = 0; p < 4; p++) {
                int idx = tid + 256*p;
                int row = idx >> 3, f = idx & 7;
                float4 v4 = *(const float4*)(wsrc + (size_t)row*NN + y0 + f*8);
                const __half2* hp = (const __half2*)&v4;
                float* d = Ws + row*68 + f*8;
                #pragma unroll
                for (int t = 0; t < 4; t++) {
                    float2 f2 = __half22float2(hp[t]);
                    d[t*2]   = f2.x;
                    d[t*2+1] = f2.y;
                }
            }
        }
        {   // Xs[d][y] = tf32(dis_y * X[y,d])
            int y = tid & 63, dblk = (tid >> 6) * 16;
            float dy = disb[y0 + y];
            const float* xr = xsrc + (size_t)(y0+y)*NC + dblk;
            #pragma unroll
            for (int u = 0; u < 4; u++) {
                float4 v = *(const float4*)(xr + u*4);
                Xs[(dblk+u*4+0)*68 + y] = to_tf32(v.x*dy);
                Xs[(dblk+u*4+1)*68 + y] = to_tf32(v.y*dy);
                Xs[(dblk+u*4+2)*68 + y] = to_tf32(v.z*dy);
                Xs[(dblk+u*4+3)*68 + y] = to_tf32(v.w*dy);
            }
        }
        __syncthreads();
        #pragma unroll
        for (int kk = 0; kk < 8; kk++) {
            uint32_t a[2][4], bf[4][2];
            #pragma unroll
            for (int i = 0; i < 2; i++) {
                const float* ap = Ws + (wm*32 + i*16)*68 + kk*8;
                a[i][0] = __float_as_uint(ap[grp*68 + tg]);
                a[i][1] = __float_as_uint(ap[(grp+8)*68 + tg]);
                a[i][2] = __float_as_uint(ap[grp*68 + tg + 4]);
                a[i][3] = __float_as_uint(ap[(grp+8)*68 + tg + 4]);
            }
            #pragma unroll
            for (int j = 0; j < 4; j++) {
                const float* bp = Xs + (wn*32 + j*8 + grp)*68 + kk*8;
                bf[j][0] = __float_as_uint(bp[tg]);
                bf[j][1] = __float_as_uint(bp[tg + 4]);
            }
            #pragma unroll
            for (int i = 0; i < 2; i++)
                #pragma unroll
                for (int j = 0; j < 4; j++)
                    mma_tf32(acc[i][j], a[i], bf[j]);
        }
    }
    #pragma unroll
    for (int i = 0; i < 2; i++) {
        #pragma unroll
        for (int u = 0; u < 2; u++) {
            int x = x0 + wm*32 + i*16 + grp + u*8;
            float dx = disb[x];
            float* dst = g_Y + (size_t)(b*NN + x)*NC + h*HD + wn*32 + tg*2;
            #pragma unroll
            for (int j = 0; j < 4; j++)
                *(float2*)(dst + j*8) = make_float2(acc[i][j][u*2]*dx, acc[i][j][u*2+1]*dx);
        }
    }
}

// ============================================================
// K5: LayerNorm over last dim (256), warp per row
// ============================================================
__global__ __launch_bounds__(256) void k5_ln(const float* __restrict__ g,
                                             const float* __restrict__ bta,
                                             float* __restrict__ out) {
    int gw = (blockIdx.x * 256 + threadIdx.x) >> 5;
    int lane = threadIdx.x & 31;
    if (gw >= NB*NN) return;
    const float* row = g_Y + (size_t)gw * NC;
    float4 v0 = *(const float4*)(row + lane*8);
    float4 v1 = *(const float4*)(row + lane*8 + 4);
    float s  = (v0.x+v0.y) + (v0.z+v0.w) + (v1.x+v1.y) + (v1.z+v1.w);
    float s2 = v0.x*v0.x + v0.y*v0.y + v0.z*v0.z + v0.w*v0.w
             + v1.x*v1.x + v1.y*v1.y + v1.z*v1.z + v1.w*v1.w;
    #pragma unroll
    for (int o = 16; o; o >>= 1) {
        s  += __shfl_xor_sync(0xffffffffu, s,  o);
        s2 += __shfl_xor_sync(0xffffffffu, s2, o);
    }
    float mu  = s * (1.f/NC);
    float var = s2 * (1.f/NC) - mu * mu;
    float inv = rsqrtf(var + 1e-5f);
    int c = lane * 8;
    float4 g0 = *(const float4*)(g + c),   g1 = *(const float4*)(g + c + 4);
    float4 b0 = *(const float4*)(bta + c), b1 = *(const float4*)(bta + c + 4);
    float4 o0, o1;
    o0.x = (v0.x-mu)*inv*g0.x + b0.x;  o0.y = (v0.y-mu)*inv*g0.y + b0.y;
    o0.z = (v0.z-mu)*inv*g0.z + b0.z;  o0.w = (v0.w-mu)*inv*g0.w + b0.w;
    o1.x = (v1.x-mu)*inv*g1.x + b1.x;  o1.y = (v1.y-mu)*inv*g1.y + b1.y;
    o1.z = (v1.z-mu)*inv*g1.z + b1.z;  o1.w = (v1.w-mu)*inv*g1.w + b1.w;
    *(float4*)(out + (size_t)gw*NC + c)     = o0;
    *(float4*)(out + (size_t)gw*NC + c + 4) = o1;
}

extern "C" void kernel_launch(void* const* d_in, const int* in_sizes, int n_in,
                              void* d_out, int out_size) {
    const float* node = (const float*)d_in[0];
    const float* adj  = (const float*)d_in[1];
    const float* Wlin = (const float*)d_in[2];
    const float* blin = (const float*)d_in[3];
    const float* Wq   = (const float*)d_in[4];
    const float* Wk   = (const float*)d_in[5];
    const float* lng  = (const float*)d_in[6];
    const float* lnb  = (const float*)d_in[7];
    float* out = (float*)d_out;

    const int smem_k2 = (2*128*68 + 4*128) * 4;     // 71,680 B
    const int smem_k4 = (128*68 + 64*68) * 4;       // 52,224 B
    cudaFuncSetAttribute(k2_att_mma, cudaFuncAttributeMaxDynamicSharedMemorySize, smem_k2);
    cudaFuncSetAttribute(k4_agg_mma, cudaFuncAttributeMaxDynamicSharedMemorySize, smem_k4);

    dim3 g1(NC/128, (NB*NN)/128, 3);
    k1_mma<<<g1, 256>>>(node, Wlin, Wq, Wk, blin);

    dim3 g2(NN/128, NB*NH);
    k2_att_mma<<<g2, 256, smem_k2>>>(adj);

    dim3 g4(NN/128, NB*NH);
    k4_agg_mma<<<g4, 256, smem_k4>>>();

    k5_ln<<<(NB*NN)/8, 256>>>(lng, lnb, out);
}

// round 8
// speedup vs baseline: 1.2262x; 1.0873x over previous
#include <cuda_runtime.h>
#include <cuda_fp16.h>
#include <cstdint>

#define NB 4
#define NN 2048
#define NC 256
#define NH 4
#define HD 64

// ---- scratch (allocation-free) ----
__device__ __half g_Xh[NB*NN*NC];
__device__ __half g_qh[NB*NN*NC];
__device__ __half g_kh[NB*NN*NC];
__device__ float  g_Y[NB*NN*NC];
__device__ float  g_dis[NB*NH*NN];
__device__ __half g_Wh[(size_t)NB*NH*NN*NN];   // 128MB fp16

__device__ __forceinline__ float to_tf32(float x) {
    uint32_t u;
    asm("cvt.rna.tf32.f32 %0, %1;" : "=r"(u) : "f"(x));
    return __uint_as_float(u);
}
__device__ __forceinline__ void mma_tf32(float c[4], const uint32_t a[4], const uint32_t b[2]) {
    asm volatile(
        "mma.sync.aligned.m16n8k8.row.col.f32.tf32.tf32.f32 "
        "{%0,%1,%2,%3}, {%4,%5,%6,%7}, {%8,%9}, {%0,%1,%2,%3};"
        : "+f"(c[0]), "+f"(c[1]), "+f"(c[2]), "+f"(c[3])
        : "r"(a[0]), "r"(a[1]), "r"(a[2]), "r"(a[3]), "r"(b[0]), "r"(b[1]));
}
__device__ __forceinline__ void mma_f16(float c[4], const uint32_t a[4], const uint32_t b[2]) {
    asm volatile(
        "mma.sync.aligned.m16n8k16.row.col.f32.f16.f16.f32 "
        "{%0,%1,%2,%3}, {%4,%5,%6,%7}, {%8,%9}, {%0,%1,%2,%3};"
        : "+f"(c[0]), "+f"(c[1]), "+f"(c[2]), "+f"(c[3])
        : "r"(a[0]), "r"(a[1]), "r"(a[2]), "r"(a[3]), "r"(b[0]), "r"(b[1]));
}
// a * sigmoid(s/8), accurate (~1e-6 rel)
__device__ __forceinline__ float sigw(float a, float s) {
    float e = __expf(-0.125f * s);
    return __fdividef(a, 1.f + e);
}

// ============================================================
// K1 (mma tf32, fp32 in, fp16 out): out = lrelu(A @ W (+bias))
// ============================================================
__global__ __launch_bounds__(256) void k1_mma(const float* __restrict__ A,
                                              const float* __restrict__ W0,
                                              const float* __restrict__ W1,
                                              const float* __restrict__ W2,
                                              const float* __restrict__ bias) {
    const int z = blockIdx.z;
    const float* Wm = (z == 0) ? W0 : ((z == 1) ? W1 : W2);
    __half* outp = (z == 0) ? g_Xh : ((z == 1) ? g_qh : g_kh);
    __shared__ float As[128*36];
    __shared__ float Bs[128*33];
    const int tid = threadIdx.x;
    const int wid = tid >> 5, lid = tid & 31;
    const int grp = lid >> 2, tg = lid & 3;
    const int wm = wid >> 1, wn = wid & 1;
    const int M0 = blockIdx.y * 128, N0 = blockIdx.x * 128;
    float acc[2][8][4] = {};
    for (int kc = 0; kc < 8; kc++) {
        const int k0 = kc * 32;
        __syncthreads();
        #pragma unroll
        for (int p = 0; p < 4; p++) {
            int idx = tid + 256*p;
            int f = idx & 7, row = idx >> 3;
            float4 v = *(const float4*)(A + (size_t)(M0 + row)*NC + k0 + f*4);
            float* d = As + row*36 + f*4;
            d[0]=to_tf32(v.x); d[1]=to_tf32(v.y); d[2]=to_tf32(v.z); d[3]=to_tf32(v.w);
        }
        #pragma unroll
        for (int p = 0; p < 4; p++) {
            int idx = tid + 256*p;
            int f = idx & 31, krow = idx >> 5;
            float4 v = *(const float4*)(Wm + (size_t)(k0 + krow)*NC + N0 + f*4);
            Bs[(f*4+0)*33 + krow] = to_tf32(v.x);
            Bs[(f*4+1)*33 + krow] = to_tf32(v.y);
            Bs[(f*4+2)*33 + krow] = to_tf32(v.z);
            Bs[(f*4+3)*33 + krow] = to_tf32(v.w);
        }
        __syncthreads();
        #pragma unroll
        for (int kk = 0; kk < 4; kk++) {
            uint32_t a[2][4], bf[8][2];
            #pragma unroll
            for (int i = 0; i < 2; i++) {
                const float* ap = As + (wm*32 + i*16 + grp)*36 + kk*8 + tg;
                a[i][0] = __float_as_uint(ap[0]);
                a[i][1] = __float_as_uint(ap[8*36]);
                a[i][2] = __float_as_uint(ap[4]);
                a[i][3] = __float_as_uint(ap[8*36 + 4]);
            }
            #pragma unroll
            for (int j = 0; j < 8; j++) {
                const float* bp = Bs + (wn*64 + j*8 + grp)*33 + kk*8 + tg;
                bf[j][0] = __float_as_uint(bp[0]);
                bf[j][1] = __float_as_uint(bp[4]);
            }
            #pragma unroll
            for (int i = 0; i < 2; i++)
                #pragma unroll
                for (int j = 0; j < 8; j++)
                    mma_tf32(acc[i][j], a[i], bf[j]);
        }
    }
    #pragma unroll
    for (int i = 0; i < 2; i++)
        #pragma unroll
        for (int u = 0; u < 2; u++) {
            int row = M0 + wm*32 + i*16 + grp + u*8;
            #pragma unroll
            for (int j = 0; j < 8; j++) {
                int col = N0 + wn*64 + j*8 + tg*2;
                float v0 = acc[i][j][u*2], v1 = acc[i][j][u*2+1];
                if (z == 0) { v0 += bias[col]; v1 += bias[col+1]; }
                v0 = (v0 >= 0.f) ? v0 : 0.01f*v0;
                v1 = (v1 >= 0.f) ? v1 : 0.01f*v1;
                *(__half2*)(outp + (size_t)row*NC + col) =
                    __float22half2_rn(make_float2(v0, v1));
            }
        }
}

// ============================================================
// K2 (mma fp16): W = adj*sigmoid(q.k/8) -> fp16; dis = rsqrt(rowsum)
// CTA 256 thr, tile 128x128, K=64 (4 x k16)
// ============================================================
__global__ __launch_bounds__(256) void k2_att_mma(const float* __restrict__ adj) {
    extern __shared__ char smraw[];
    __half* qs  = (__half*)smraw;                 // 128*72 halves
    __half* ks  = qs + 128*72;                    // 128*72 halves
    float*  red = (float*)(ks + 128*72);          // 512 floats
    const int tid = threadIdx.x;
    const int wid = tid >> 5, lid = tid & 31;
    const int grp = lid >> 2, tg = lid & 3;
    const int wm = wid >> 2, wn = wid & 3;
    const int bh = blockIdx.y;
    const int b = bh >> 2, h = bh & 3;
    const int x0 = blockIdx.x * 128;
    const int srow = tid >> 1, spart = tid & 1;

    {   // stage q once: 128 rows x 64 halves (row stride 72)
        const uint4* g = (const uint4*)(g_qh + ((size_t)(b*NN + x0 + srow))*NC + h*HD + spart*32);
        uint4* s = (uint4*)(qs + srow*72 + spart*32);
        s[0]=g[0]; s[1]=g[1]; s[2]=g[2]; s[3]=g[3];
    }
    const __half* ksrc  = g_kh + (size_t)b*NN*NC + h*HD;
    const float*  abase = adj + (size_t)b*NN*NN;
    __half* wbase = g_Wh + (size_t)bh*NN*NN;
    float dsum[4][2] = {};

    for (int yt = 0; yt < NN/128; yt++) {
        const int y0 = yt * 128;
        __syncthreads();
        {   // stage k tile
            const uint4* g = (const uint4*)(ksrc + (size_t)(y0 + srow)*NC + spart*32);
            uint4* s = (uint4*)(ks + srow*72 + spart*32);
            s[0]=g[0]; s[1]=g[1]; s[2]=g[2]; s[3]=g[3];
        }
        __syncthreads();
        float acc[4][4][4] = {};
        #pragma unroll
        for (int kk = 0; kk < 4; kk++) {
            uint32_t a[4][4], bf[4][2];
            #pragma unroll
            for (int i = 0; i < 4; i++) {
                const __half* ap = qs + (wm*64 + i*16)*72 + kk*16;
                a[i][0] = *(const uint32_t*)(ap + grp*72 + 2*tg);
                a[i][1] = *(const uint32_t*)(ap + (grp+8)*72 + 2*tg);
                a[i][2] = *(const uint32_t*)(ap + grp*72 + 2*tg + 8);
                a[i][3] = *(const uint32_t*)(ap + (grp+8)*72 + 2*tg + 8);
            }
            #pragma unroll
            for (int j = 0; j < 4; j++) {
                const __half* bp = ks + (wn*32 + j*8 + grp)*72 + kk*16;
                bf[j][0] = *(const uint32_t*)(bp + 2*tg);
                bf[j][1] = *(const uint32_t*)(bp + 2*tg + 8);
            }
            #pragma unroll
            for (int i = 0; i < 4; i++)
                #pragma unroll
                for (int j = 0; j < 4; j++)
                    mma_f16(acc[i][j], a[i], bf[j]);
        }
        // epilogue: sigmoid*adj -> fp16 W, accumulate degree in fp32
        #pragma unroll
        for (int i = 0; i < 4; i++) {
            #pragma unroll
            for (int u = 0; u < 2; u++) {
                int xr = x0 + wm*64 + i*16 + grp + u*8;
                const float* ar = abase + (size_t)xr*NN + y0 + wn*32 + tg*2;
                __half* wr = wbase + (size_t)xr*NN + y0 + wn*32 + tg*2;
                float lsum = 0.f;
                #pragma unroll
                for (int j = 0; j < 4; j++) {
                    float2 av = *(const float2*)(ar + j*8);
                    float w0 = sigw(av.x, acc[i][j][u*2+0]);
                    float w1 = sigw(av.y, acc[i][j][u*2+1]);
                    *(__half2*)(wr + j*8) = __float22half2_rn(make_float2(w0, w1));
                    lsum += w0 + w1;
                }
                dsum[i][u] += lsum;
            }
        }
    }
    #pragma unroll
    for (int i = 0; i < 4; i++)
        #pragma unroll
        for (int u = 0; u < 2; u++) {
            float v = dsum[i][u];
            v += __shfl_xor_sync(0xffffffffu, v, 1);
            v += __shfl_xor_sync(0xffffffffu, v, 2);
            if (tg == 0) red[wn*128 + wm*64 + i*16 + grp + u*8] = v;
        }
    __syncthreads();
    if (tid < 128) {
        float v = red[tid] + red[128+tid] + red[256+tid] + red[384+tid];
        g_dis[bh*NN + x0 + tid] = (v > 0.f) ? rsqrtf(v) : 0.f;
    }
}

// ============================================================
// K4 (mma fp16): Y[x,d] = dis_x * sum_y W[x,y]*dis_y*X[y,d]
// CTA 256 thr, tile 128x64, K-chunks of 64 over y
// ============================================================
__global__ __launch_bounds__(256) void k4_agg_mma() {
    extern __shared__ char smraw[];
    __half* Ws = (__half*)smraw;      // 128*72 halves
    __half* Xs = Ws + 128*72;         // 64*72 halves
    const int tid = threadIdx.x;
    const int wid = tid >> 5, lid = tid & 31;
    const int grp = lid >> 2, tg = lid & 3;
    const int wm = wid >> 1, wn = wid & 1;
    const int bh = blockIdx.y;
    const int b = bh >> 2, h = bh & 3;
    const int x0 = blockIdx.x * 128;
    const __half* wsrc = g_Wh + (size_t)bh*NN*NN + (size_t)x0*NN;
    const __half* xsrc = g_Xh + (size_t)b*NN*NC + h*HD;
    const float*  disb = g_dis + bh*NN;
    const int srow = tid >> 1, spart = tid & 1;
    const int sy = tid & 63, sdblk = (tid >> 6) * 16;
    float acc[2][4][4] = {};
    for (int y0 = 0; y0 < NN; y0 += 64) {
        __syncthreads();
        {   // Ws: 128 rows x 64 halves
            const uint4* g = (const uint4*)(wsrc + (size_t)srow*NN + y0 + spart*32);
            uint4* s = (uint4*)(Ws + srow*72 + spart*32);
            s[0]=g[0]; s[1]=g[1]; s[2]=g[2]; s[3]=g[3];
        }
        {   // Xs[d][y] = fp16(dis_y * X[y,d]) (transposed, fp32 math)
            float dy = disb[y0 + sy];
            const __half* xr = xsrc + (size_t)(y0 + sy)*NC + sdblk;
            #pragma unroll
            for (int u = 0; u < 8; u++) {
                float2 f = __half22float2(*(const __half2*)(xr + u*2));
                Xs[(sdblk + 2*u)*72 + sy]   = __float2half(f.x * dy);
                Xs[(sdblk + 2*u+1)*72 + sy] = __float2half(f.y * dy);
            }
        }
        __syncthreads();
        #pragma unroll
        for (int kk = 0; kk < 4; kk++) {
            uint32_t a[2][4], bf[4][2];
            #pragma unroll
            for (int i = 0; i < 2; i++) {
                const __half* ap = Ws + (wm*32 + i*16)*72 + kk*16;
                a[i][0] = *(const uint32_t*)(ap + grp*72 + 2*tg);
                a[i][1] = *(const uint32_t*)(ap + (grp+8)*72 + 2*tg);
                a[i][2] = *(const uint32_t*)(ap + grp*72 + 2*tg + 8);
                a[i][3] = *(const uint32_t*)(ap + (grp+8)*72 + 2*tg + 8);
            }
            #pragma unroll
            for (int j = 0; j < 4; j++) {
                const __half* bp = Xs + (wn*32 + j*8 + grp)*72 + kk*16;
                bf[j][0] = *(const uint32_t*)(bp + 2*tg);
                bf[j][1] = *(const uint32_t*)(bp + 2*tg + 8);
            }
            #pragma unroll
            for (int i = 0; i < 2; i++)
                #pragma unroll
                for (int j = 0; j < 4; j++)
                    mma_f16(acc[i][j], a[i], bf[j]);
        }
    }
    #pragma unroll
    for (int i = 0; i < 2; i++) {
        #pragma unroll
        for (int u = 0; u < 2; u++) {
            int x = x0 + wm*32 + i*16 + grp + u*8;
            float dx = disb[x];
            float* dst = g_Y + (size_t)(b*NN + x)*NC + h*HD + wn*32 + tg*2;
            #pragma unroll
            for (int j = 0; j < 4; j++)
                *(float2*)(dst + j*8) = make_float2(acc[i][j][u*2]*dx, acc[i][j][u*2+1]*dx);
        }
    }
}

// ============================================================
// K5: LayerNorm over last dim (256), warp per row
// ============================================================
__global__ __launch_bounds__(256) void k5_ln(const float* __restrict__ g,
                                             const float* __restrict__ bta,
                                             float* __restrict__ out) {
    int gw = (blockIdx.x * 256 + threadIdx.x) >> 5;
    int lane = threadIdx.x & 31;
    if (gw >= NB*NN) return;
    const float* row = g_Y + (size_t)gw * NC;
    float4 v0 = *(const float4*)(row + lane*8);
    float4 v1 = *(const float4*)(row + lane*8 + 4);
    float s  = (v0.x+v0.y) + (v0.z+v0.w) + (v1.x+v1.y) + (v1.z+v1.w);
    float s2 = v0.x*v0.x + v0.y*v0.y + v0.z*v0.z + v0.w*v0.w
             + v1.x*v1.x + v1.y*v1.y + v1.z*v1.z + v1.w*v1.w;
    #pragma unroll
    for (int o = 16; o; o >>= 1) {
        s  += __shfl_xor_sync(0xffffffffu, s,  o);
        s2 += __shfl_xor_sync(0xffffffffu, s2, o);
    }
    float mu  = s * (1.f/NC);
    float var = s2 * (1.f/NC) - mu * mu;
    float inv = rsqrtf(var + 1e-5f);
    int c = lane * 8;
    float4 g0 = *(const float4*)(g + c),   g1 = *(const float4*)(g + c + 4);
    float4 b0 = *(const float4*)(bta + c), b1 = *(const float4*)(bta + c + 4);
    float4 o0, o1;
    o0.x = (v0.x-mu)*inv*g0.x + b0.x;  o0.y = (v0.y-mu)*inv*g0.y + b0.y;
    o0.z = (v0.z-mu)*inv*g0.z + b0.z;  o0.w = (v0.w-mu)*inv*g0.w + b0.w;
    o1.x = (v1.x-mu)*inv*g1.x + b1.x;  o1.y = (v1.y-mu)*inv*g1.y + b1.y;
    o1.z = (v1.z-mu)*inv*g1.z + b1.z;  o1.w = (v1.w-mu)*inv*g1.w + b1.w;
    *(float4*)(out + (size_t)gw*NC + c)     = o0;
    *(float4*)(out + (size_t)gw*NC + c + 4) = o1;
}

extern "C" void kernel_launch(void* const* d_in, const int* in_sizes, int n_in,
                              void* d_out, int out_size) {
    const float* node = (const float*)d_in[0];
    const float* adj  = (const float*)d_in[1];
    const float* Wlin = (const float*)d_in[2];
    const float* blin = (const float*)d_in[3];
    const float* Wq   = (const float*)d_in[4];
    const float* Wk   = (const float*)d_in[5];
    const float* lng  = (const float*)d_in[6];
    const float* lnb  = (const float*)d_in[7];
    float* out = (float*)d_out;

    const int smem_k2 = (2*128*72)*2 + 512*4;   // 38,912 B
    const int smem_k4 = (128*72 + 64*72)*2;     // 27,648 B

    dim3 g1(NC/128, (NB*NN)/128, 3);
    k1_mma<<<g1, 256>>>(node, Wlin, Wq, Wk, blin);

    dim3 g2(NN/128, NB*NH);
    k2_att_mma<<<g2, 256, smem_k2>>>(adj);

    dim3 g4(NN/128, NB*NH);
    k4_agg_mma<<<g4, 256, smem_k4>>>();

    k5_ln<<<(NB*NN)/8, 256>>>(lng, lnb, out);
}

// round 9
// speedup vs baseline: 1.6847x; 1.3739x over previous
#include <cuda_runtime.h>
#include <cuda_fp16.h>
#include <cstdint>

#define NB 4
#define NN 2048
#define NC 256
#define NH 4
#define HD 64

// ---- scratch (allocation-free) ----
__device__ __half g_Xh[NB*NN*NC];
__device__ __half g_qh[NB*NN*NC];
__device__ __half g_kh[NB*NN*NC];
__device__ __half g_XT[NB*NH*HD*NN];           // [bh][d][y], dis_y folded (4.2MB)
__device__ float  g_Y[NB*NN*NC];
__device__ float  g_dis[NB*NH*NN];
__device__ __half g_Wh[(size_t)NB*NH*NN*NN];   // 128MB fp16

__device__ __forceinline__ float to_tf32(float x) {
    uint32_t u;
    asm("cvt.rna.tf32.f32 %0, %1;" : "=r"(u) : "f"(x));
    return __uint_as_float(u);
}
__device__ __forceinline__ void mma_tf32(float c[4], const uint32_t a[4], const uint32_t b[2]) {
    asm volatile(
        "mma.sync.aligned.m16n8k8.row.col.f32.tf32.tf32.f32 "
        "{%0,%1,%2,%3}, {%4,%5,%6,%7}, {%8,%9}, {%0,%1,%2,%3};"
        : "+f"(c[0]), "+f"(c[1]), "+f"(c[2]), "+f"(c[3])
        : "r"(a[0]), "r"(a[1]), "r"(a[2]), "r"(a[3]), "r"(b[0]), "r"(b[1]));
}
__device__ __forceinline__ void mma_f16(float c[4], const uint32_t a[4], const uint32_t b[2]) {
    asm volatile(
        "mma.sync.aligned.m16n8k16.row.col.f32.f16.f16.f32 "
        "{%0,%1,%2,%3}, {%4,%5,%6,%7}, {%8,%9}, {%0,%1,%2,%3};"
        : "+f"(c[0]), "+f"(c[1]), "+f"(c[2]), "+f"(c[3])
        : "r"(a[0]), "r"(a[1]), "r"(a[2]), "r"(a[3]), "r"(b[0]), "r"(b[1]));
}
// a * sigmoid(s/8), accurate (~1e-6 rel)
__device__ __forceinline__ float sigw(float a, float s) {
    float e = __expf(-0.125f * s);
    return __fdividef(a, 1.f + e);
}

// ============================================================
// K1 (mma tf32, fp32 in, fp16 out): out = lrelu(A @ W (+bias))
// ============================================================
__global__ __launch_bounds__(256) void k1_mma(const float* __restrict__ A,
                                              const float* __restrict__ W0,
                                              const float* __restrict__ W1,
                                              const float* __restrict__ W2,
                                              const float* __restrict__ bias) {
    const int z = blockIdx.z;
    const float* Wm = (z == 0) ? W0 : ((z == 1) ? W1 : W2);
    __half* outp = (z == 0) ? g_Xh : ((z == 1) ? g_qh : g_kh);
    __shared__ float As[128*36];
    __shared__ float Bs[128*33];
    const int tid = threadIdx.x;
    const int wid = tid >> 5, lid = tid & 31;
    const int grp = lid >> 2, tg = lid & 3;
    const int wm = wid >> 1, wn = wid & 1;
    const int M0 = blockIdx.y * 128, N0 = blockIdx.x * 128;
    float acc[2][8][4] = {};
    for (int kc = 0; kc < 8; kc++) {
        const int k0 = kc * 32;
        __syncthreads();
        #pragma unroll
        for (int p = 0; p < 4; p++) {
            int idx = tid + 256*p;
            int f = idx & 7, row = idx >> 3;
            float4 v = *(const float4*)(A + (size_t)(M0 + row)*NC + k0 + f*4);
            float* d = As + row*36 + f*4;
            d[0]=to_tf32(v.x); d[1]=to_tf32(v.y); d[2]=to_tf32(v.z); d[3]=to_tf32(v.w);
        }
        #pragma unroll
        for (int p = 0; p < 4; p++) {
            int idx = tid + 256*p;
            int f = idx & 31, krow = idx >> 5;
            float4 v = *(const float4*)(Wm + (size_t)(k0 + krow)*NC + N0 + f*4);
            Bs[(f*4+0)*33 + krow] = to_tf32(v.x);
            Bs[(f*4+1)*33 + krow] = to_tf32(v.y);
            Bs[(f*4+2)*33 + krow] = to_tf32(v.z);
            Bs[(f*4+3)*33 + krow] = to_tf32(v.w);
        }
        __syncthreads();
        #pragma unroll
        for (int kk = 0; kk < 4; kk++) {
            uint32_t a[2][4], bf[8][2];
            #pragma unroll
            for (int i = 0; i < 2; i++) {
                const float* ap = As + (wm*32 + i*16 + grp)*36 + kk*8 + tg;
                a[i][0] = __float_as_uint(ap[0]);
                a[i][1] = __float_as_uint(ap[8*36]);
                a[i][2] = __float_as_uint(ap[4]);
                a[i][3] = __float_as_uint(ap[8*36 + 4]);
            }
            #pragma unroll
            for (int j = 0; j < 8; j++) {
                const float* bp = Bs + (wn*64 + j*8 + grp)*33 + kk*8 + tg;
                bf[j][0] = __float_as_uint(bp[0]);
                bf[j][1] = __float_as_uint(bp[4]);
            }
            #pragma unroll
            for (int i = 0; i < 2; i++)
                #pragma unroll
                for (int j = 0; j < 8; j++)
                    mma_tf32(acc[i][j], a[i], bf[j]);
        }
    }
    #pragma unroll
    for (int i = 0; i < 2; i++)
        #pragma unroll
        for (int u = 0; u < 2; u++) {
            int row = M0 + wm*32 + i*16 + grp + u*8;
            #pragma unroll
            for (int j = 0; j < 8; j++) {
                int col = N0 + wn*64 + j*8 + tg*2;
                float v0 = acc[i][j][u*2], v1 = acc[i][j][u*2+1];
                if (z == 0) { v0 += bias[col]; v1 += bias[col+1]; }
                v0 = (v0 >= 0.f) ? v0 : 0.01f*v0;
                v1 = (v1 >= 0.f) ? v1 : 0.01f*v1;
                *(__half2*)(outp + (size_t)row*NC + col) =
                    __float22half2_rn(make_float2(v0, v1));
            }
        }
}

// ============================================================
// K2 (mma fp16 + smem restage): W = adj*sigmoid(q.k/8) -> fp16 (coalesced),
// dis = rsqrt(rowsum). CTA 256 thr, tile 128x128, K=64.
// ============================================================
__global__ __launch_bounds__(256, 2) void k2_att_mma(const float* __restrict__ adj) {
    extern __shared__ char smraw[];
    __half* qs  = (__half*)smraw;                 // 128*72 halves
    __half* ks  = qs + 128*72;                    // 128*72 halves
    float*  S   = (float*)(ks + 128*72);          // 128*132 floats
    float*  red = S + 128*132;                    // 128 floats
    const int tid = threadIdx.x;
    const int wid = tid >> 5, lid = tid & 31;
    const int grp = lid >> 2, tg = lid & 3;
    const int wm = wid >> 2, wn = wid & 3;
    const int bh = blockIdx.y;
    const int b = bh >> 2, h = bh & 3;
    const int x0 = blockIdx.x * 128;
    const int srow = tid >> 1, spart = tid & 1;
    const int rl8 = lid >> 3, rl = lid & 7;       // restage: row sub, col lane

    {   // stage q once
        const uint4* g = (const uint4*)(g_qh + ((size_t)(b*NN + x0 + srow))*NC + h*HD + spart*32);
        uint4* s = (uint4*)(qs + srow*72 + spart*32);
        s[0]=g[0]; s[1]=g[1]; s[2]=g[2]; s[3]=g[3];
    }
    if (tid < 128) red[tid] = 0.f;

    const __half* ksrc  = g_kh + (size_t)b*NN*NC + h*HD;
    const float*  abase = adj + (size_t)b*NN*NN;
    __half* wbase = g_Wh + (size_t)bh*NN*NN;

    for (int yt = 0; yt < NN/128; yt++) {
        const int y0 = yt * 128;
        {   // stage k tile
            const uint4* g = (const uint4*)(ksrc + (size_t)(y0 + srow)*NC + spart*32);
            uint4* s = (uint4*)(ks + srow*72 + spart*32);
            s[0]=g[0]; s[1]=g[1]; s[2]=g[2]; s[3]=g[3];
        }
        __syncthreads();
        float acc[4][4][4] = {};
        #pragma unroll
        for (int kk = 0; kk < 4; kk++) {
            uint32_t a[4][4], bf[4][2];
            #pragma unroll
            for (int i = 0; i < 4; i++) {
                const __half* ap = qs + (wm*64 + i*16)*72 + kk*16;
                a[i][0] = *(const uint32_t*)(ap + grp*72 + 2*tg);
                a[i][1] = *(const uint32_t*)(ap + (grp+8)*72 + 2*tg);
                a[i][2] = *(const uint32_t*)(ap + grp*72 + 2*tg + 8);
                a[i][3] = *(const uint32_t*)(ap + (grp+8)*72 + 2*tg + 8);
            }
            #pragma unroll
            for (int j = 0; j < 4; j++) {
                const __half* bp = ks + (wn*32 + j*8 + grp)*72 + kk*16;
                bf[j][0] = *(const uint32_t*)(bp + 2*tg);
                bf[j][1] = *(const uint32_t*)(bp + 2*tg + 8);
            }
            #pragma unroll
            for (int i = 0; i < 4; i++)
                #pragma unroll
                for (int j = 0; j < 4; j++)
                    mma_f16(acc[i][j], a[i], bf[j]);
        }
        // dump S frags to smem (scattered, but smem-cheap)
        #pragma unroll
        for (int i = 0; i < 4; i++) {
            int xr = wm*64 + i*16 + grp;
            #pragma unroll
            for (int j = 0; j < 4; j++) {
                int col = wn*32 + j*8 + 2*tg;
                *(float2*)(S + xr*132 + col)     = make_float2(acc[i][j][0], acc[i][j][1]);
                *(float2*)(S + (xr+8)*132 + col) = make_float2(acc[i][j][2], acc[i][j][3]);
            }
        }
        __syncthreads();
        // coalesced epilogue: rows re-mapped row-major across the CTA
        #pragma unroll
        for (int p = 0; p < 4; p++) {
            int xr = p*32 + wid*4 + rl8;
            const float* Srow = S + xr*132;
            const float* arow = abase + (size_t)(x0 + xr)*NN + y0;
            __half* wrow = wbase + (size_t)(x0 + xr)*NN + y0;
            float lsum = 0.f;
            #pragma unroll
            for (int c = 0; c < 4; c++) {
                int col = c*32 + rl*4;
                float4 sv = *(const float4*)(Srow + col);
                float4 av = *(const float4*)(arow + col);
                float w0 = sigw(av.x, sv.x);
                float w1 = sigw(av.y, sv.y);
                float w2 = sigw(av.z, sv.z);
                float w3 = sigw(av.w, sv.w);
                __half2 h0 = __float22half2_rn(make_float2(w0, w1));
                __half2 h1 = __float22half2_rn(make_float2(w2, w3));
                uint2 st = make_uint2(*(uint32_t*)&h0, *(uint32_t*)&h1);
                *(uint2*)(wrow + col) = st;          // 8B contiguous store
                lsum += (w0 + w1) + (w2 + w3);
            }
            lsum += __shfl_xor_sync(0xffffffffu, lsum, 1);
            lsum += __shfl_xor_sync(0xffffffffu, lsum, 2);
            lsum += __shfl_xor_sync(0xffffffffu, lsum, 4);
            if (rl == 0) red[xr] += lsum;            // single writer per row
        }
    }
    __syncthreads();
    if (tid < 128) {
        float v = red[tid];
        g_dis[bh*NN + x0 + tid] = (v > 0.f) ? rsqrtf(v) : 0.f;
    }
}

// ============================================================
// K3x: g_XT[bh][d][y] = fp16(dis_y * X[b,y,h*64+d])  (transpose + fold)
// ============================================================
__global__ __launch_bounds__(256) void k3_xt() {
    __shared__ __half T[64*72];
    const int tid = threadIdx.x;
    const int yt = blockIdx.x, bh = blockIdx.y;
    const int b = bh >> 2, h = bh & 3;
    const int y0 = yt * 64;
    {   // load rows (y-major), fold dis_y in fp32
        int yr = tid >> 2, cp = tid & 3;
        float dy = g_dis[bh*NN + y0 + yr];
        const __half* src = g_Xh + ((size_t)(b*NN + y0 + yr))*NC + h*HD + cp*16;
        __half* dst = T + yr*72 + cp*16;
        #pragma unroll
        for (int u = 0; u < 8; u++) {
            float2 f = __half22float2(((const __half2*)src)[u]);
            ((__half2*)dst)[u] = __float22half2_rn(make_float2(f.x*dy, f.y*dy));
        }
    }
    __syncthreads();
    {   // write transposed rows (d-major), coalesced
        int dr = tid >> 2, cp = tid & 3;
        __half* dst = g_XT + ((size_t)bh*HD + dr)*NN + y0 + cp*16;
        __half tmp[16];
        #pragma unroll
        for (int u = 0; u < 16; u++)
            tmp[u] = T[(cp*16 + u)*72 + dr];
        *(uint4*)(dst)     = *(uint4*)(tmp);
        *(uint4*)(dst + 8) = *(uint4*)(tmp + 8);
    }
}

// ============================================================
// K4 (mma fp16, double-buffered, pure-copy staging):
// Y[x,d] = dis_x * sum_y W[x,y] * XT[d,y]
// ============================================================
__global__ __launch_bounds__(256, 2) void k4_agg_mma() {
    extern __shared__ char smraw[];
    __half* Ws = (__half*)smraw;          // 2 x 128*72
    __half* Xs = Ws + 2*128*72;           // 2 x 64*72
    const int tid = threadIdx.x;
    const int wid = tid >> 5, lid = tid & 31;
    const int grp = lid >> 2, tg = lid & 3;
    const int wm = wid >> 1, wn = wid & 1;
    const int bh = blockIdx.y;
    const int b = bh >> 2, h = bh & 3;
    const int x0 = blockIdx.x * 128;
    const __half* wsrc  = g_Wh + (size_t)bh*NN*NN + (size_t)x0*NN;
    const __half* xtsrc = g_XT + (size_t)bh*HD*NN;
    const float*  disb  = g_dis + bh*NN;
    const int wrow = tid >> 1, wpart = tid & 1;
    const int xrow = tid >> 2, xpart = tid & 3;

    uint4 wreg[4], xreg[2];
    {   // prologue: LDG tile 0
        const uint4* gw = (const uint4*)(wsrc + (size_t)wrow*NN + wpart*32);
        wreg[0]=gw[0]; wreg[1]=gw[1]; wreg[2]=gw[2]; wreg[3]=gw[3];
        const uint4* gx = (const uint4*)(xtsrc + (size_t)xrow*NN + xpart*16);
        xreg[0]=gx[0]; xreg[1]=gx[1];
    }
    float acc[2][4][4] = {};
    for (int it = 0; it < NN/64; it++) {
        __half* Wb = Ws + (it & 1) * 128*72;
        __half* Xb = Xs + (it & 1) * 64*72;
        {   // STS current tile
            uint4* s = (uint4*)(Wb + wrow*72 + wpart*32);
            s[0]=wreg[0]; s[1]=wreg[1]; s[2]=wreg[2]; s[3]=wreg[3];
            uint4* sx = (uint4*)(Xb + xrow*72 + xpart*16);
            sx[0]=xreg[0]; sx[1]=xreg[1];
        }
        __syncthreads();
        if (it < NN/64 - 1) {   // prefetch next tile into regs
            int y0 = (it + 1) * 64;
            const uint4* gw = (const uint4*)(wsrc + (size_t)wrow*NN + y0 + wpart*32);
            wreg[0]=gw[0]; wreg[1]=gw[1]; wreg[2]=gw[2]; wreg[3]=gw[3];
            const uint4* gx = (const uint4*)(xtsrc + (size_t)xrow*NN + y0 + xpart*16);
            xreg[0]=gx[0]; xreg[1]=gx[1];
        }
        #pragma unroll
        for (int kk = 0; kk < 4; kk++) {
            uint32_t a[2][4], bf[4][2];
            #pragma unroll
            for (int i = 0; i < 2; i++) {
                const __half* ap = Wb + (wm*32 + i*16)*72 + kk*16;
                a[i][0] = *(const uint32_t*)(ap + grp*72 + 2*tg);
                a[i][1] = *(const uint32_t*)(ap + (grp+8)*72 + 2*tg);
                a[i][2] = *(const uint32_t*)(ap + grp*72 + 2*tg + 8);
                a[i][3] = *(const uint32_t*)(ap + (grp+8)*72 + 2*tg + 8);
            }
            #pragma unroll
            for (int j = 0; j < 4; j++) {
                const __half* bp = Xb + (wn*32 + j*8 + grp)*72 + kk*16;
                bf[j][0] = *(const uint32_t*)(bp + 2*tg);
                bf[j][1] = *(const uint32_t*)(bp + 2*tg + 8);
            }
            #pragma unroll
            for (int i = 0; i < 2; i++)
                #pragma unroll
                for (int j = 0; j < 4; j++)
                    mma_f16(acc[i][j], a[i], bf[j]);
        }
    }
    #pragma unroll
    for (int i = 0; i < 2; i++) {
        #pragma unroll
        for (int u = 0; u < 2; u++) {
            int x = x0 + wm*32 + i*16 + grp + u*8;
            float dx = disb[x];
            float* dst = g_Y + (size_t)(b*NN + x)*NC + h*HD + wn*32 + tg*2;
            #pragma unroll
            for (int j = 0; j < 4; j++)
                *(float2*)(dst + j*8) = make_float2(acc[i][j][u*2]*dx, acc[i][j][u*2+1]*dx);
        }
    }
}

// ============================================================
// K5: LayerNorm over last dim (256), warp per row
// ============================================================
__global__ __launch_bounds__(256) void k5_ln(const float* __restrict__ g,
                                             const float* __restrict__ bta,
                                             float* __restrict__ out) {
    int gw = (blockIdx.x * 256 + threadIdx.x) >> 5;
    int lane = threadIdx.x & 31;
    if (gw >= NB*NN) return;
    const float* row = g_Y + (size_t)gw * NC;
    float4 v0 = *(const float4*)(row + lane*8);
    float4 v1 = *(const float4*)(row + lane*8 + 4);
    float s  = (v0.x+v0.y) + (v0.z+v0.w) + (v1.x+v1.y) + (v1.z+v1.w);
    float s2 = v0.x*v0.x + v0.y*v0.y + v0.z*v0.z + v0.w*v0.w
             + v1.x*v1.x + v1.y*v1.y + v1.z*v1.z + v1.w*v1.w;
    #pragma unroll
    for (int o = 16; o; o >>= 1) {
        s  += __shfl_xor_sync(0xffffffffu, s,  o);
        s2 += __shfl_xor_sync(0xffffffffu, s2, o);
    }
    float mu  = s * (1.f/NC);
    float var = s2 * (1.f/NC) - mu * mu;
    float inv = rsqrtf(var + 1e-5f);
    int c = lane * 8;
    float4 g0 = *(const float4*)(g + c),   g1 = *(const float4*)(g + c + 4);
    float4 b0 = *(const float4*)(bta + c), b1 = *(const float4*)(bta + c + 4);
    float4 o0, o1;
    o0.x = (v0.x-mu)*inv*g0.x + b0.x;  o0.y = (v0.y-mu)*inv*g0.y + b0.y;
    o0.z = (v0.z-mu)*inv*g0.z + b0.z;  o0.w = (v0.w-mu)*inv*g0.w + b0.w;
    o1.x = (v1.x-mu)*inv*g1.x + b1.x;  o1.y = (v1.y-mu)*inv*g1.y + b1.y;
    o1.z = (v1.z-mu)*inv*g1.z + b1.z;  o1.w = (v1.w-mu)*inv*g1.w + b1.w;
    *(float4*)(out + (size_t)gw*NC + c)     = o0;
    *(float4*)(out + (size_t)gw*NC + c + 4) = o1;
}

extern "C" void kernel_launch(void* const* d_in, const int* in_sizes, int n_in,
                              void* d_out, int out_size) {
    const float* node = (const float*)d_in[0];
    const float* adj  = (const float*)d_in[1];
    const float* Wlin = (const float*)d_in[2];
    const float* blin = (const float*)d_in[3];
    const float* Wq   = (const float*)d_in[4];
    const float* Wk   = (const float*)d_in[5];
    const float* lng  = (const float*)d_in[6];
    const float* lnb  = (const float*)d_in[7];
    float* out = (float*)d_out;

    const int smem_k2 = 2*128*72*2 + 128*132*4 + 128*4;   // 104,960 B
    const int smem_k4 = (2*128*72 + 2*64*72) * 2;         // 55,296 B
    cudaFuncSetAttribute(k2_att_mma, cudaFuncAttributeMaxDynamicSharedMemorySize, smem_k2);
    cudaFuncSetAttribute(k4_agg_mma, cudaFuncAttributeMaxDynamicSharedMemorySize, smem_k4);

    dim3 g1(NC/128, (NB*NN)/128, 3);
    k1_mma<<<g1, 256>>>(node, Wlin, Wq, Wk, blin);

    dim3 g2(NN/128, NB*NH);
    k2_att_mma<<<g2, 256, smem_k2>>>(adj);

    dim3 g3(NN/64, NB*NH);
    k3_xt<<<g3, 256>>>();

    dim3 g4(NN/128, NB*NH);
    k4_agg_mma<<<g4, 256, smem_k4>>>();

    k5_ln<<<(NB*NN)/8, 256>>>(lng, lnb, out);
}

// round 10
// speedup vs baseline: 1.7373x; 1.0312x over previous
#include <cuda_runtime.h>
#include <cuda_fp16.h>
#include <cstdint>

#define NB 4
#define NN 2048
#define NC 256
#define NH 4
#define HD 64

// ---- scratch (allocation-free) ----
__device__ __half g_Xh[NB*NN*NC];
__device__ __half g_qh[NB*NN*NC];
__device__ __half g_kh[NB*NN*NC];
__device__ __half g_XT[NB*NH*HD*NN];           // [bh][d][y], dis_y folded (4.2MB)
__device__ float  g_Y[NB*NN*NC];
__device__ float  g_dis[NB*NH*NN];
__device__ __half g_Wh[(size_t)NB*NH*NN*NN];   // 128MB fp16

__device__ __forceinline__ float to_tf32(float x) {
    uint32_t u;
    asm("cvt.rna.tf32.f32 %0, %1;" : "=r"(u) : "f"(x));
    return __uint_as_float(u);
}
__device__ __forceinline__ void mma_tf32(float c[4], const uint32_t a[4], const uint32_t b[2]) {
    asm volatile(
        "mma.sync.aligned.m16n8k8.row.col.f32.tf32.tf32.f32 "
        "{%0,%1,%2,%3}, {%4,%5,%6,%7}, {%8,%9}, {%0,%1,%2,%3};"
        : "+f"(c[0]), "+f"(c[1]), "+f"(c[2]), "+f"(c[3])
        : "r"(a[0]), "r"(a[1]), "r"(a[2]), "r"(a[3]), "r"(b[0]), "r"(b[1]));
}
__device__ __forceinline__ void mma_f16(float c[4], const uint32_t a[4], const uint32_t b[2]) {
    asm volatile(
        "mma.sync.aligned.m16n8k16.row.col.f32.f16.f16.f32 "
        "{%0,%1,%2,%3}, {%4,%5,%6,%7}, {%8,%9}, {%0,%1,%2,%3};"
        : "+f"(c[0]), "+f"(c[1]), "+f"(c[2]), "+f"(c[3])
        : "r"(a[0]), "r"(a[1]), "r"(a[2]), "r"(a[3]), "r"(b[0]), "r"(b[1]));
}
__device__ __forceinline__ uint32_t smem_cast(const void* p) {
    return (uint32_t)__cvta_generic_to_shared(p);
}
__device__ __forceinline__ void ldsm_x4(uint32_t& r0, uint32_t& r1, uint32_t& r2, uint32_t& r3,
                                        uint32_t addr) {
    asm volatile("ldmatrix.sync.aligned.m8n8.x4.shared.b16 {%0,%1,%2,%3}, [%4];"
        : "=r"(r0), "=r"(r1), "=r"(r2), "=r"(r3) : "r"(addr));
}
__device__ __forceinline__ void cp16(void* s, const void* g) {
    asm volatile("cp.async.cg.shared.global [%0], [%1], 16;"
        :: "r"(smem_cast(s)), "l"(g));
}
#define CP_COMMIT() asm volatile("cp.async.commit_group;" ::: "memory")
// a * sigmoid(s/8), accurate (~1e-6 rel)
__device__ __forceinline__ float sigw(float a, float s) {
    float e = __expf(-0.125f * s);
    return __fdividef(a, 1.f + e);
}

// ============================================================
// K1 (mma tf32, fp32 in, fp16 out): out = lrelu(A @ W (+bias))
// ============================================================
__global__ __launch_bounds__(256) void k1_mma(const float* __restrict__ A,
                                              const float* __restrict__ W0,
                                              const float* __restrict__ W1,
                                              const float* __restrict__ W2,
                                              const float* __restrict__ bias) {
    const int z = blockIdx.z;
    const float* Wm = (z == 0) ? W0 : ((z == 1) ? W1 : W2);
    __half* outp = (z == 0) ? g_Xh : ((z == 1) ? g_qh : g_kh);
    __shared__ float As[128*36];
    __shared__ float Bs[128*33];
    const int tid = threadIdx.x;
    const int wid = tid >> 5, lid = tid & 31;
    const int grp = lid >> 2, tg = lid & 3;
    const int wm = wid >> 1, wn = wid & 1;
    const int M0 = blockIdx.y * 128, N0 = blockIdx.x * 128;
    float acc[2][8][4] = {};
    for (int kc = 0; kc < 8; kc++) {
        const int k0 = kc * 32;
        __syncthreads();
        #pragma unroll
        for (int p = 0; p < 4; p++) {
            int idx = tid + 256*p;
            int f = idx & 7, row = idx >> 3;
            float4 v = *(const float4*)(A + (size_t)(M0 + row)*NC + k0 + f*4);
            float* d = As + row*36 + f*4;
            d[0]=to_tf32(v.x); d[1]=to_tf32(v.y); d[2]=to_tf32(v.z); d[3]=to_tf32(v.w);
        }
        #pragma unroll
        for (int p = 0; p < 4; p++) {
            int idx = tid + 256*p;
            int f = idx & 31, krow = idx >> 5;
            float4 v = *(const float4*)(Wm + (size_t)(k0 + krow)*NC + N0 + f*4);
            Bs[(f*4+0)*33 + krow] = to_tf32(v.x);
            Bs[(f*4+1)*33 + krow] = to_tf32(v.y);
            Bs[(f*4+2)*33 + krow] = to_tf32(v.z);
            Bs[(f*4+3)*33 + krow] = to_tf32(v.w);
        }
        __syncthreads();
        #pragma unroll
        for (int kk = 0; kk < 4; kk++) {
            uint32_t a[2][4], bf[8][2];
            #pragma unroll
            for (int i = 0; i < 2; i++) {
                const float* ap = As + (wm*32 + i*16 + grp)*36 + kk*8 + tg;
                a[i][0] = __float_as_uint(ap[0]);
                a[i][1] = __float_as_uint(ap[8*36]);
                a[i][2] = __float_as_uint(ap[4]);
                a[i][3] = __float_as_uint(ap[8*36 + 4]);
            }
            #pragma unroll
            for (int j = 0; j < 8; j++) {
                const float* bp = Bs + (wn*64 + j*8 + grp)*33 + kk*8 + tg;
                bf[j][0] = __float_as_uint(bp[0]);
                bf[j][1] = __float_as_uint(bp[4]);
            }
            #pragma unroll
            for (int i = 0; i < 2; i++)
                #pragma unroll
                for (int j = 0; j < 8; j++)
                    mma_tf32(acc[i][j], a[i], bf[j]);
        }
    }
    #pragma unroll
    for (int i = 0; i < 2; i++)
        #pragma unroll
        for (int u = 0; u < 2; u++) {
            int row = M0 + wm*32 + i*16 + grp + u*8;
            #pragma unroll
            for (int j = 0; j < 8; j++) {
                int col = N0 + wn*64 + j*8 + tg*2;
                float v0 = acc[i][j][u*2], v1 = acc[i][j][u*2+1];
                if (z == 0) { v0 += bias[col]; v1 += bias[col+1]; }
                v0 = (v0 >= 0.f) ? v0 : 0.01f*v0;
                v1 = (v1 >= 0.f) ? v1 : 0.01f*v1;
                *(__half2*)(outp + (size_t)row*NC + col) =
                    __float22half2_rn(make_float2(v0, v1));
            }
        }
}

// ============================================================
// K2 (mma fp16, ldmatrix frags, smem restage): W = adj*sigmoid(q.k/8) -> fp16,
// dis = rsqrt(rowsum). CTA 256 thr, tile 128x128, K=64.
// ============================================================
__global__ __launch_bounds__(256, 2) void k2_att_mma(const float* __restrict__ adj) {
    extern __shared__ char smraw[];
    __half* qs  = (__half*)smraw;                 // 128*72 halves
    __half* ks  = qs + 128*72;                    // 128*72 halves
    float*  S   = (float*)(ks + 128*72);          // 128*132 floats
    float*  red = S + 128*132;                    // 128 floats
    const int tid = threadIdx.x;
    const int wid = tid >> 5, lid = tid & 31;
    const int wm = wid >> 2, wn = wid & 3;
    const int bh = blockIdx.y;
    const int b = bh >> 2, h = bh & 3;
    const int x0 = blockIdx.x * 128;
    const int srow = tid >> 1, spart = tid & 1;
    const int rl8 = lid >> 3, rl = lid & 7;

    // ldmatrix lane addressing offsets
    const int a_row = lid & 15, a_koff = (lid >> 4) * 8;
    const int b_row = ((lid >> 4) & 1) * 8 + (lid & 7), b_koff = ((lid >> 3) & 1) * 8;

    {   // stage q once
        const uint4* g = (const uint4*)(g_qh + ((size_t)(b*NN + x0 + srow))*NC + h*HD + spart*32);
        uint4* s = (uint4*)(qs + srow*72 + spart*32);
        s[0]=g[0]; s[1]=g[1]; s[2]=g[2]; s[3]=g[3];
    }
    if (tid < 128) red[tid] = 0.f;

    const __half* ksrc  = g_kh + (size_t)b*NN*NC + h*HD;
    const float*  abase = adj + (size_t)b*NN*NN;
    __half* wbase = g_Wh + (size_t)bh*NN*NN;

    for (int yt = 0; yt < NN/128; yt++) {
        const int y0 = yt * 128;
        {   // stage k tile
            const uint4* g = (const uint4*)(ksrc + (size_t)(y0 + srow)*NC + spart*32);
            uint4* s = (uint4*)(ks + srow*72 + spart*32);
            s[0]=g[0]; s[1]=g[1]; s[2]=g[2]; s[3]=g[3];
        }
        __syncthreads();
        float acc[4][4][4] = {};
        #pragma unroll
        for (int kk = 0; kk < 4; kk++) {
            uint32_t a[4][4], bf[4][2];
            #pragma unroll
            for (int i = 0; i < 4; i++) {
                uint32_t ad = smem_cast(qs + (wm*64 + i*16 + a_row)*72 + kk*16 + a_koff);
                ldsm_x4(a[i][0], a[i][1], a[i][2], a[i][3], ad);
            }
            #pragma unroll
            for (int jj = 0; jj < 2; jj++) {
                uint32_t bd = smem_cast(ks + (wn*32 + jj*16 + b_row)*72 + kk*16 + b_koff);
                ldsm_x4(bf[2*jj][0], bf[2*jj][1], bf[2*jj+1][0], bf[2*jj+1][1], bd);
            }
            #pragma unroll
            for (int i = 0; i < 4; i++)
                #pragma unroll
                for (int j = 0; j < 4; j++)
                    mma_f16(acc[i][j], a[i], bf[j]);
        }
        // dump S frags to smem
        {
            const int grp = lid >> 2, tg = lid & 3;
            #pragma unroll
            for (int i = 0; i < 4; i++) {
                int xr = wm*64 + i*16 + grp;
                #pragma unroll
                for (int j = 0; j < 4; j++) {
                    int col = wn*32 + j*8 + 2*tg;
                    *(float2*)(S + xr*132 + col)     = make_float2(acc[i][j][0], acc[i][j][1]);
                    *(float2*)(S + (xr+8)*132 + col) = make_float2(acc[i][j][2], acc[i][j][3]);
                }
            }
        }
        __syncthreads();
        // coalesced epilogue
        #pragma unroll
        for (int p = 0; p < 4; p++) {
            int xr = p*32 + wid*4 + rl8;
            const float* Srow = S + xr*132;
            const float* arow = abase + (size_t)(x0 + xr)*NN + y0;
            __half* wrow = wbase + (size_t)(x0 + xr)*NN + y0;
            float lsum = 0.f;
            #pragma unroll
            for (int c = 0; c < 4; c++) {
                int col = c*32 + rl*4;
                float4 sv = *(const float4*)(Srow + col);
                float4 av = *(const float4*)(arow + col);
                float w0 = sigw(av.x, sv.x);
                float w1 = sigw(av.y, sv.y);
                float w2 = sigw(av.z, sv.z);
                float w3 = sigw(av.w, sv.w);
                __half2 h0 = __float22half2_rn(make_float2(w0, w1));
                __half2 h1 = __float22half2_rn(make_float2(w2, w3));
                uint2 st = make_uint2(*(uint32_t*)&h0, *(uint32_t*)&h1);
                *(uint2*)(wrow + col) = st;
                lsum += (w0 + w1) + (w2 + w3);
            }
            lsum += __shfl_xor_sync(0xffffffffu, lsum, 1);
            lsum += __shfl_xor_sync(0xffffffffu, lsum, 2);
            lsum += __shfl_xor_sync(0xffffffffu, lsum, 4);
            if (rl == 0) red[xr] += lsum;
        }
    }
    __syncthreads();
    if (tid < 128) {
        float v = red[tid];
        g_dis[bh*NN + x0 + tid] = (v > 0.f) ? rsqrtf(v) : 0.f;
    }
}

// ============================================================
// K3x: g_XT[bh][d][y] = fp16(dis_y * X[b,y,h*64+d])
// ============================================================
__global__ __launch_bounds__(256) void k3_xt() {
    __shared__ __half T[64*72];
    const int tid = threadIdx.x;
    const int yt = blockIdx.x, bh = blockIdx.y;
    const int b = bh >> 2, h = bh & 3;
    const int y0 = yt * 64;
    {
        int yr = tid >> 2, cp = tid & 3;
        float dy = g_dis[bh*NN + y0 + yr];
        const __half* src = g_Xh + ((size_t)(b*NN + y0 + yr))*NC + h*HD + cp*16;
        __half* dst = T + yr*72 + cp*16;
        #pragma unroll
        for (int u = 0; u < 8; u++) {
            float2 f = __half22float2(((const __half2*)src)[u]);
            ((__half2*)dst)[u] = __float22half2_rn(make_float2(f.x*dy, f.y*dy));
        }
    }
    __syncthreads();
    {
        int dr = tid >> 2, cp = tid & 3;
        __half* dst = g_XT + ((size_t)bh*HD + dr)*NN + y0 + cp*16;
        __half tmp[16];
        #pragma unroll
        for (int u = 0; u < 16; u++)
            tmp[u] = T[(cp*16 + u)*72 + dr];
        *(uint4*)(dst)     = *(uint4*)(tmp);
        *(uint4*)(dst + 8) = *(uint4*)(tmp + 8);
    }
}

// ============================================================
// K4 (mma fp16, cp.async double-buffer, ldmatrix frags):
// Y[x,d] = dis_x * sum_y W[x,y] * XT[d,y]
// ============================================================
__global__ __launch_bounds__(256, 2) void k4_agg_mma() {
    extern __shared__ char smraw[];
    __half* Ws = (__half*)smraw;          // 2 x 128*72
    __half* Xs = Ws + 2*128*72;           // 2 x 64*72
    const int tid = threadIdx.x;
    const int wid = tid >> 5, lid = tid & 31;
    const int grp = lid >> 2, tg = lid & 3;
    const int wm = wid >> 1, wn = wid & 1;
    const int bh = blockIdx.y;
    const int b = bh >> 2, h = bh & 3;
    const int x0 = blockIdx.x * 128;
    const __half* wsrc  = g_Wh + (size_t)bh*NN*NN + (size_t)x0*NN;
    const __half* xtsrc = g_XT + (size_t)bh*HD*NN;
    const float*  disb  = g_dis + bh*NN;
    const int wrow = tid >> 1, wpart = tid & 1;
    const int xrow = tid >> 2, xpart = tid & 3;
    const int a_row = lid & 15, a_koff = (lid >> 4) * 8;
    const int b_row = ((lid >> 4) & 1) * 8 + (lid & 7), b_koff = ((lid >> 3) & 1) * 8;

    // issue tile `it` into buffer it&1
    auto issue = [&](int it) {
        int y0 = it * 64;
        __half* Wb = Ws + (it & 1) * 128*72;
        __half* Xb = Xs + (it & 1) * 64*72;
        const __half* gw = wsrc + (size_t)wrow*NN + y0 + wpart*32;
        __half* sw = Wb + wrow*72 + wpart*32;
        #pragma unroll
        for (int u = 0; u < 4; u++) cp16(sw + u*8, gw + u*8);
        const __half* gx = xtsrc + (size_t)xrow*NN + y0 + xpart*16;
        __half* sx = Xb + xrow*72 + xpart*16;
        #pragma unroll
        for (int u = 0; u < 2; u++) cp16(sx + u*8, gx + u*8);
        CP_COMMIT();
    };

    issue(0);
    float acc[2][4][4] = {};
    for (int it = 0; it < NN/64; it++) {
        if (it < NN/64 - 1) {
            issue(it + 1);
            asm volatile("cp.async.wait_group 1;" ::: "memory");
        } else {
            asm volatile("cp.async.wait_group 0;" ::: "memory");
        }
        __syncthreads();
        __half* Wb = Ws + (it & 1) * 128*72;
        __half* Xb = Xs + (it & 1) * 64*72;
        #pragma unroll
        for (int kk = 0; kk < 4; kk++) {
            uint32_t a[2][4], bf[4][2];
            #pragma unroll
            for (int i = 0; i < 2; i++) {
                uint32_t ad = smem_cast(Wb + (wm*32 + i*16 + a_row)*72 + kk*16 + a_koff);
                ldsm_x4(a[i][0], a[i][1], a[i][2], a[i][3], ad);
            }
            #pragma unroll
            for (int jj = 0; jj < 2; jj++) {
                uint32_t bd = smem_cast(Xb + (wn*32 + jj*16 + b_row)*72 + kk*16 + b_koff);
                ldsm_x4(bf[2*jj][0], bf[2*jj][1], bf[2*jj+1][0], bf[2*jj+1][1], bd);
            }
            #pragma unroll
            for (int i = 0; i < 2; i++)
                #pragma unroll
                for (int j = 0; j < 4; j++)
                    mma_f16(acc[i][j], a[i], bf[j]);
        }
        __syncthreads();
    }
    #pragma unroll
    for (int i = 0; i < 2; i++) {
        #pragma unroll
        for (int u = 0; u < 2; u++) {
            int x = x0 + wm*32 + i*16 + grp + u*8;
            float dx = disb[x];
            float* dst = g_Y + (size_t)(b*NN + x)*NC + h*HD + wn*32 + tg*2;
            #pragma unroll
            for (int j = 0; j < 4; j++)
                *(float2*)(dst + j*8) = make_float2(acc[i][j][u*2]*dx, acc[i][j][u*2+1]*dx);
        }
    }
}

// ============================================================
// K5: LayerNorm over last dim (256), warp per row
// ============================================================
__global__ __launch_bounds__(256) void k5_ln(const float* __restrict__ g,
                                             const float* __restrict__ bta,
                                             float* __restrict__ out) {
    int gw = (blockIdx.x * 256 + threadIdx.x) >> 5;
    int lane = threadIdx.x & 31;
    if (gw >= NB*NN) return;
    const float* row = g_Y + (size_t)gw * NC;
    float4 v0 = *(const float4*)(row + lane*8);
    float4 v1 = *(const float4*)(row + lane*8 + 4);
    float s  = (v0.x+v0.y) + (v0.z+v0.w) + (v1.x+v1.y) + (v1.z+v1.w);
    float s2 = v0.x*v0.x + v0.y*v0.y + v0.z*v0.z + v0.w*v0.w
             + v1.x*v1.x + v1.y*v1.y + v1.z*v1.z + v1.w*v1.w;
    #pragma unroll
    for (int o = 16; o; o >>= 1) {
        s  += __shfl_xor_sync(0xffffffffu, s,  o);
        s2 += __shfl_xor_sync(0xffffffffu, s2, o);
    }
    float mu  = s * (1.f/NC);
    float var = s2 * (1.f/NC) - mu * mu;
    float inv = rsqrtf(var + 1e-5f);
    int c = lane * 8;
    float4 g0 = *(const float4*)(g + c),   g1 = *(const float4*)(g + c + 4);
    float4 b0 = *(const float4*)(bta + c), b1 = *(const float4*)(bta + c + 4);
    float4 o0, o1;
    o0.x = (v0.x-mu)*inv*g0.x + b0.x;  o0.y = (v0.y-mu)*inv*g0.y + b0.y;
    o0.z = (v0.z-mu)*inv*g0.z + b0.z;  o0.w = (v0.w-mu)*inv*g0.w + b0.w;
    o1.x = (v1.x-mu)*inv*g1.x + b1.x;  o1.y = (v1.y-mu)*inv*g1.y + b1.y;
    o1.z = (v1.z-mu)*inv*g1.z + b1.z;  o1.w = (v1.w-mu)*inv*g1.w + b1.w;
    *(float4*)(out + (size_t)gw*NC + c)     = o0;
    *(float4*)(out + (size_t)gw*NC + c + 4) = o1;
}

extern "C" void kernel_launch(void* const* d_in, const int* in_sizes, int n_in,
                              void* d_out, int out_size) {
    const float* node = (const float*)d_in[0];
    const float* adj  = (const float*)d_in[1];
    const float* Wlin = (const float*)d_in[2];
    const float* blin = (const float*)d_in[3];
    const float* Wq   = (const float*)d_in[4];
    const float* Wk   = (const float*)d_in[5];
    const float* lng  = (const float*)d_in[6];
    const float* lnb  = (const float*)d_in[7];
    float* out = (float*)d_out;

    const int smem_k2 = 2*128*72*2 + 128*132*4 + 128*4;   // 104,960 B
    const int smem_k4 = (2*128*72 + 2*64*72) * 2;         // 55,296 B
    cudaFuncSetAttribute(k2_att_mma, cudaFuncAttributeMaxDynamicSharedMemorySize, smem_k2);
    cudaFuncSetAttribute(k4_agg_mma, cudaFuncAttributeMaxDynamicSharedMemorySize, smem_k4);

    dim3 g1(NC/128, (NB*NN)/128, 3);
    k1_mma<<<g1, 256>>>(node, Wlin, Wq, Wk, blin);

    dim3 g2(NN/128, NB*NH);
    k2_att_mma<<<g2, 256, smem_k2>>>(adj);

    dim3 g3(NN/64, NB*NH);
    k3_xt<<<g3, 256>>>();

    dim3 g4(NN/128, NB*NH);
    k4_agg_mma<<<g4, 256, smem_k4>>>();

    k5_ln<<<(NB*NN)/8, 256>>>(lng, lnb, out);
}